// round 13
// baseline (speedup 1.0000x reference)
#include <cuda_runtime.h>
#include <cuda_fp16.h>
#include <cstdint>

// ---------------- problem shape ----------------
#define Bn 4
#define Hn 16
#define Sn 2048
#define Dn 64
#define BHn (Bn*Hn)
#define MQ 128
#define TN 64
#define NTILES (Sn/TN)    // 32
#define C2 0.18033688011112042f   // 0.125 * log2(e)

// ---------------- global scratch ----------------
__device__ __half QH_g[(size_t)BHn * Sn * Dn];
__device__ __half KH_g[(size_t)BHn * Sn * Dn];
__device__ __half VH_g[(size_t)BHn * Sn * Dn];
__device__ float  BIAS_g[Bn * Sn];
__device__ float  INV_g[(size_t)BHn * Sn];

// ---------------- helpers ----------------
__device__ __forceinline__ uint32_t swz(uint32_t o) { return o ^ ((o >> 3) & 0x70); }
__device__ __forceinline__ uint32_t s2u(const void* p) {
    uint32_t a;
    asm("{ .reg .u64 t; cvta.to.shared.u64 t, %1; cvt.u32.u64 %0, t; }" : "=r"(a) : "l"(p));
    return a;
}
__device__ __forceinline__ uint32_t ph2(float a, float b) {
    __half2 h = __floats2half2_rn(a, b);
    return *reinterpret_cast<uint32_t*>(&h);
}
__device__ __forceinline__ float ex2f(float x) {
    float r; asm("ex2.approx.f32 %0, %1;" : "=f"(r) : "f"(x)); return r;
}
__device__ __forceinline__ void ldsm4(uint32_t* r, uint32_t a) {
    asm volatile("ldmatrix.sync.aligned.m8n8.x4.shared.b16 {%0,%1,%2,%3}, [%4];"
        : "=r"(r[0]), "=r"(r[1]), "=r"(r[2]), "=r"(r[3]) : "r"(a));
}
__device__ __forceinline__ void ldsm4t(uint32_t* r, uint32_t a) {
    asm volatile("ldmatrix.sync.aligned.m8n8.x4.trans.shared.b16 {%0,%1,%2,%3}, [%4];"
        : "=r"(r[0]), "=r"(r[1]), "=r"(r[2]), "=r"(r[3]) : "r"(a));
}
__device__ __forceinline__ void mma16816(float* d, const uint32_t* a, const uint32_t* b) {
    asm volatile("mma.sync.aligned.m16n8k16.row.col.f32.f16.f16.f32 "
        "{%0,%1,%2,%3},{%4,%5,%6,%7},{%8,%9},{%0,%1,%2,%3};"
        : "+f"(d[0]), "+f"(d[1]), "+f"(d[2]), "+f"(d[3])
        : "r"(a[0]), "r"(a[1]), "r"(a[2]), "r"(a[3]), "r"(b[0]), "r"(b[1]));
}
__device__ __forceinline__ void cpa16(uint32_t dst, const void* src) {
    asm volatile("cp.async.ca.shared.global [%0], [%1], 16;" :: "r"(dst), "l"(src));
}
#define CPA_COMMIT() asm volatile("cp.async.commit_group;" ::: "memory")
#define CPA_WAIT0()  asm volatile("cp.async.wait_group 0;" ::: "memory")

// ---------------- prep kernels ----------------
__global__ void prep_cvt(const float4* __restrict__ Qs, const float4* __restrict__ Ks,
                         const float4* __restrict__ Vs) {
    const size_t n1 = (size_t)BHn * Sn * Dn / 8;
    size_t i = (size_t)blockIdx.x * blockDim.x + threadIdx.x;
    size_t tsel = i / n1, off = i - tsel * n1;
    const float4* src = tsel == 0 ? Qs : (tsel == 1 ? Ks : Vs);
    __half* dst = tsel == 0 ? QH_g : (tsel == 1 ? KH_g : VH_g);
    float4 a = src[off * 2], b = src[off * 2 + 1];
    uint4 o;
    o.x = ph2(a.x, a.y); o.y = ph2(a.z, a.w);
    o.z = ph2(b.x, b.y); o.w = ph2(b.z, b.w);
    reinterpret_cast<uint4*>(dst)[off] = o;
}
__global__ void prep_bias(const int* __restrict__ Mk) {
    int i = blockIdx.x * blockDim.x + threadIdx.x;
    if (i < Bn * Sn) BIAS_g[i] = Mk[i] ? 0.f : -1e30f;
}

// ================= Kernel A: rowsums at high occupancy =================
// 8 warps x 16 query rows (round-5 verified pass-1 shape), TN=64 double-buffered
#define A_QH   0
#define A_KH   16384
#define A_BIAS 32768
#define A_RS   40960
#define A_SMEM 41472

__global__ __launch_bounds__(256, 3)
void rowsum_k(void)
{
    extern __shared__ char smem[];
    const uint32_t su = s2u(smem);
    const int tid = threadIdx.x, w = tid >> 5, lane = tid & 31;
    const int bh = blockIdx.y, b = bh >> 4;
    const int q0 = blockIdx.x * MQ;
    const __half* Kg = KH_g + (size_t)bh * Sn * Dn;

    // group 0: Q (16KB) + bias (8KB)
    {
        const __half* qg = QH_g + ((size_t)bh * Sn + q0) * Dn;
        #pragma unroll
        for (int it = 0; it < 4; ++it) {
            int ch = tid + it * 256;
            int r = ch >> 3, c8 = ch & 7;
            cpa16(su + A_QH + swz((uint32_t)(r * 128 + c8 * 16)), qg + r * Dn + c8 * 8);
        }
        const float* bg = BIAS_g + b * Sn;
        #pragma unroll
        for (int it = 0; it < 2; ++it) {
            int ch = tid + it * 256;
            cpa16(su + A_BIAS + (uint32_t)ch * 16, bg + ch * 4);
        }
        CPA_COMMIT();
    }
    // group 1: K tile 0
    #pragma unroll
    for (int it = 0; it < 2; ++it) {
        int ch = tid + it * 256;
        int r = ch >> 3, c8 = ch & 7;
        cpa16(su + A_KH + swz((uint32_t)(r * 128 + c8 * 16)), Kg + r * Dn + c8 * 8);
    }
    CPA_COMMIT();
    CPA_WAIT0();
    __syncthreads();

    const float* bias = (const float*)(smem + A_BIAS);
    const int qr = w * 16 + (lane & 7) + ((lane >> 3) & 1) * 8;
    const uint32_t qcs = ((lane >> 4) & 1) * 16;
    const int krb = (lane & 7) + ((lane >> 4) & 1) * 8;
    const uint32_t kcs = ((lane >> 3) & 1) * 16;
    const int cb0 = (lane & 3) * 2;

    uint32_t qf[4][4];
    #pragma unroll
    for (int ks = 0; ks < 4; ++ks)
        ldsm4(qf[ks], su + A_QH + swz((uint32_t)(qr * 128 + ks * 32) + qcs));

    float rs0 = 0.f, rs1 = 0.f;
    for (int t = 0; t < NTILES; ++t) {
        if (t + 1 < NTILES) {
            const __half* kg = Kg + (size_t)(t + 1) * TN * Dn;
            uint32_t buf = su + A_KH + ((t + 1) & 1) * 8192;
            #pragma unroll
            for (int it = 0; it < 2; ++it) {
                int ch = tid + it * 256;
                int r = ch >> 3, c8 = ch & 7;
                cpa16(buf + swz((uint32_t)(r * 128 + c8 * 16)), kg + r * Dn + c8 * 8);
            }
            CPA_COMMIT();
        }
        const uint32_t kbuf = su + A_KH + (t & 1) * 8192;
        float c_[8][4];
        #pragma unroll
        for (int nt = 0; nt < 8; ++nt)
            #pragma unroll
            for (int i = 0; i < 4; ++i) c_[nt][i] = 0.f;
        #pragma unroll
        for (int ks = 0; ks < 4; ++ks) {
            #pragma unroll
            for (int pr = 0; pr < 4; ++pr) {
                uint32_t bh_[4];
                ldsm4(bh_, kbuf + swz((uint32_t)((pr * 16 + krb) * 128 + ks * 32) + kcs));
                mma16816(c_[2 * pr],     qf[ks], bh_);
                mma16816(c_[2 * pr + 1], qf[ks], bh_ + 2);
            }
        }
        const float* bp = bias + t * TN + cb0;
        #pragma unroll
        for (int nt = 0; nt < 8; ++nt) {
            float2 bb = *(const float2*)(bp + nt * 8);
            rs0 += ex2f(fmaf(c_[nt][0], C2, bb.x)) + ex2f(fmaf(c_[nt][1], C2, bb.y));
            rs1 += ex2f(fmaf(c_[nt][2], C2, bb.x)) + ex2f(fmaf(c_[nt][3], C2, bb.y));
        }
        if (t + 1 < NTILES) { CPA_WAIT0(); __syncthreads(); }
    }
    rs0 += __shfl_xor_sync(~0u, rs0, 1); rs0 += __shfl_xor_sync(~0u, rs0, 2);
    rs1 += __shfl_xor_sync(~0u, rs1, 1); rs1 += __shfl_xor_sync(~0u, rs1, 2);
    float* rsm = (float*)(smem + A_RS);
    if ((lane & 3) == 0) {
        rsm[w * 16 + (lane >> 2)] = rs0;
        rsm[w * 16 + 8 + (lane >> 2)] = rs1;
    }
    __syncthreads();
    if (tid < MQ)
        INV_g[(size_t)bh * Sn + q0 + tid] = 1.0f / rsm[tid];
}

// ================= Kernel B: attn + O (round-12 pass 2) =================
#define NT 128
#define SM_QH   0
#define SM_KH   16384
#define SM_VH   32768
#define SM_BIAS 49152
#define SMEM_B  57344      // x3 CTAs = 172032

__device__ __forceinline__ void issue_tile(uint32_t bufbase, const __half* __restrict__ g, int tid) {
    #pragma unroll
    for (int it = 0; it < 4; ++it) {
        int ch = tid + it * NT;
        int r = ch >> 3, c8 = ch & 7;
        cpa16(bufbase + swz((uint32_t)(r * 128 + c8 * 16)), g + r * Dn + c8 * 8);
    }
}

__global__ __launch_bounds__(NT, 3)
void attn_hmma(float* __restrict__ Out, float* __restrict__ Attn)
{
    extern __shared__ char smem[];
    const uint32_t su = s2u(smem);
    const int tid = threadIdx.x, w = tid >> 5, lane = tid & 31;
    const int bh = blockIdx.y, b = bh >> 4;
    const int q0 = blockIdx.x * MQ;

    const __half* Kg = KH_g + (size_t)bh * Sn * Dn;
    const __half* Vg = VH_g + (size_t)bh * Sn * Dn;

    // group 0: Q tile + bias
    {
        const __half* qg = QH_g + ((size_t)bh * Sn + q0) * Dn;
        #pragma unroll
        for (int it = 0; it < 8; ++it) {
            int ch = tid + it * NT;
            int r = ch >> 3, c8 = ch & 7;
            cpa16(su + SM_QH + swz((uint32_t)(r * 128 + c8 * 16)), qg + r * Dn + c8 * 8);
        }
        const float* bg = BIAS_g + b * Sn;
        #pragma unroll
        for (int it = 0; it < 4; ++it) {
            int ch = tid + it * NT;
            cpa16(su + SM_BIAS + (uint32_t)ch * 16, bg + ch * 4);
        }
        CPA_COMMIT();
    }
    // group 1: K0 + V0
    issue_tile(su + SM_KH, Kg, tid);
    issue_tile(su + SM_VH, Vg, tid);
    CPA_COMMIT();

    const uint32_t qcs = ((lane >> 4) & 1) * 16;
    const int krb = (lane & 7) + ((lane >> 4) & 1) * 8;
    const uint32_t kcs = ((lane >> 3) & 1) * 16;
    const int cb0 = (lane & 3) * 2;
    int qr[2];
    qr[0] = w * 16 + (lane & 7) + ((lane >> 3) & 1) * 8;
    qr[1] = qr[0] + 64;

    // inv from kernel A (overlaps cp.async)
    float inv_[2][2];
    {
        const float* ig = INV_g + (size_t)bh * Sn + q0;
        #pragma unroll
        for (int mb = 0; mb < 2; ++mb) {
            inv_[mb][0] = __ldg(ig + (w + 4 * mb) * 16 + (lane >> 2));
            inv_[mb][1] = __ldg(ig + (w + 4 * mb) * 16 + 8 + (lane >> 2));
        }
    }
    CPA_WAIT0();
    __syncthreads();
    const float* bias = (const float*)(smem + SM_BIAS);

    float O[2][8][4];
    #pragma unroll
    for (int mb = 0; mb < 2; ++mb)
        #pragma unroll
        for (int j = 0; j < 8; ++j)
            #pragma unroll
            for (int i = 0; i < 4; ++i) O[mb][j][i] = 0.f;

    const int vrb = (lane & 7) + ((lane >> 3) & 1) * 8;
    const uint32_t vcs = ((lane >> 4) & 1) * 16;
    float* ar[2][2];
    #pragma unroll
    for (int mb = 0; mb < 2; ++mb) {
        ar[mb][0] = Attn + ((size_t)bh * Sn + q0 + (w + 4 * mb) * 16 + (lane >> 2)) * Sn;
        ar[mb][1] = ar[mb][0] + (size_t)8 * Sn;
    }

    for (int t = 0; t < NTILES; ++t) {
        if (t + 1 < NTILES) {
            issue_tile(su + SM_KH + ((t + 1) & 1) * 8192, Kg + (size_t)(t + 1) * TN * Dn, tid);
            issue_tile(su + SM_VH + ((t + 1) & 1) * 8192, Vg + (size_t)(t + 1) * TN * Dn, tid);
            CPA_COMMIT();
        }
        const uint32_t kbuf = su + SM_KH + (t & 1) * 8192;
        const uint32_t vbuf = su + SM_VH + (t & 1) * 8192;

        float c_[2][8][4];
        #pragma unroll
        for (int mb = 0; mb < 2; ++mb)
            #pragma unroll
            for (int nt = 0; nt < 8; ++nt)
                #pragma unroll
                for (int i = 0; i < 4; ++i) c_[mb][nt][i] = 0.f;
        #pragma unroll
        for (int ks = 0; ks < 4; ++ks) {
            uint32_t ah[2][4];
            #pragma unroll
            for (int mb = 0; mb < 2; ++mb)
                ldsm4(ah[mb], su + SM_QH + swz((uint32_t)(qr[mb] * 128 + ks * 32) + qcs));
            #pragma unroll
            for (int pr = 0; pr < 4; ++pr) {
                uint32_t bh_[4];
                ldsm4(bh_, kbuf + swz((uint32_t)((pr * 16 + krb) * 128 + ks * 32) + kcs));
                #pragma unroll
                for (int mb = 0; mb < 2; ++mb) {
                    mma16816(c_[mb][2 * pr],     ah[mb], bh_);
                    mma16816(c_[mb][2 * pr + 1], ah[mb], bh_ + 2);
                }
            }
        }
        uint32_t PH[2][8][2];
        const float* bp = bias + t * TN + cb0;
        #pragma unroll
        for (int mb = 0; mb < 2; ++mb) {
            #pragma unroll
            for (int nt = 0; nt < 8; ++nt) {
                int col = t * TN + nt * 8 + cb0;
                float2 bb = *(const float2*)(bp + nt * 8);
                float p0 = ex2f(fmaf(c_[mb][nt][0], C2, bb.x)) * inv_[mb][0];
                float p1 = ex2f(fmaf(c_[mb][nt][1], C2, bb.y)) * inv_[mb][0];
                float p2 = ex2f(fmaf(c_[mb][nt][2], C2, bb.x)) * inv_[mb][1];
                float p3 = ex2f(fmaf(c_[mb][nt][3], C2, bb.y)) * inv_[mb][1];
                *(float2*)(ar[mb][0] + col) = make_float2(p0, p1);
                *(float2*)(ar[mb][1] + col) = make_float2(p2, p3);
                PH[mb][nt][0] = ph2(p0, p1);
                PH[mb][nt][1] = ph2(p2, p3);
            }
        }
        #pragma unroll
        for (int kp = 0; kp < 4; ++kp) {
            uint32_t pah[2][4];
            #pragma unroll
            for (int mb = 0; mb < 2; ++mb) {
                pah[mb][0] = PH[mb][2*kp][0];   pah[mb][1] = PH[mb][2*kp][1];
                pah[mb][2] = PH[mb][2*kp+1][0]; pah[mb][3] = PH[mb][2*kp+1][1];
            }
            int vrow = kp * 16 + vrb;
            #pragma unroll
            for (int dp = 0; dp < 4; ++dp) {
                uint32_t vb[4];
                ldsm4t(vb, vbuf + swz((uint32_t)(vrow * 128 + dp * 32) + vcs));
                #pragma unroll
                for (int mb = 0; mb < 2; ++mb) {
                    mma16816(O[mb][2 * dp],     pah[mb], vb);
                    mma16816(O[mb][2 * dp + 1], pah[mb], vb + 2);
                }
            }
        }
        if (t + 1 < NTILES) { CPA_WAIT0(); __syncthreads(); }
    }

    #pragma unroll
    for (int mb = 0; mb < 2; ++mb) {
        float* orow0 = Out + ((size_t)bh * Sn + q0 + (w + 4 * mb) * 16 + (lane >> 2)) * Dn;
        float* orow1 = orow0 + 8 * Dn;
        #pragma unroll
        for (int dt = 0; dt < 8; ++dt) {
            int col = dt * 8 + cb0;
            *(float2*)(orow0 + col) = make_float2(O[mb][dt][0], O[mb][dt][1]);
            *(float2*)(orow1 + col) = make_float2(O[mb][dt][2], O[mb][dt][3]);
        }
    }
}

extern "C" void kernel_launch(void* const* d_in, const int* in_sizes, int n_in,
                              void* d_out, int out_size)
{
    const float* Q    = (const float*)d_in[0];
    const float* K    = (const float*)d_in[1];
    const float* V    = (const float*)d_in[2];
    const int*   mask = (const int*)d_in[3];

    float* Out  = (float*)d_out;
    float* Attn = Out + (size_t)BHn * Sn * Dn;

    const size_t nchunks = (size_t)3 * BHn * Sn * Dn / 8;
    prep_cvt<<<(int)(nchunks / 256), 256>>>((const float4*)Q, (const float4*)K, (const float4*)V);
    prep_bias<<<(Bn * Sn + 255) / 256, 256>>>(mask);

    cudaFuncSetAttribute(rowsum_k, cudaFuncAttributeMaxDynamicSharedMemorySize, A_SMEM);
    cudaFuncSetAttribute(attn_hmma, cudaFuncAttributeMaxDynamicSharedMemorySize, SMEM_B);

    dim3 grid(Sn / MQ, BHn);
    rowsum_k<<<grid, 256, A_SMEM>>>();
    attn_hmma<<<grid, NT, SMEM_B>>>(Out, Attn);
}

// round 14
// speedup vs baseline: 1.0931x; 1.0931x over previous
#include <cuda_runtime.h>
#include <cuda_fp16.h>
#include <cstdint>

// ---------------- problem shape ----------------
#define Bn 4
#define Hn 16
#define Sn 2048
#define Dn 64
#define BHn (Bn*Hn)
#define MQ 128
#define TN 64
#define NTILES (Sn/TN)    // 32
#define C2 0.18033688011112042f   // 0.125 * log2(e)

// ---------------- global scratch ----------------
__device__ __half QH_g[(size_t)BHn * Sn * Dn];
__device__ __half KH_g[(size_t)BHn * Sn * Dn];
__device__ __half VH_g[(size_t)BHn * Sn * Dn];
__device__ float  BIAS_g[Bn * Sn];
__device__ float  INV_g[(size_t)BHn * Sn];

// ---------------- helpers ----------------
__device__ __forceinline__ uint32_t swz(uint32_t o) { return o ^ ((o >> 3) & 0x70); }
__device__ __forceinline__ uint32_t s2u(const void* p) {
    uint32_t a;
    asm("{ .reg .u64 t; cvta.to.shared.u64 t, %1; cvt.u32.u64 %0, t; }" : "=r"(a) : "l"(p));
    return a;
}
__device__ __forceinline__ uint32_t ph2(float a, float b) {
    __half2 h = __floats2half2_rn(a, b);
    return *reinterpret_cast<uint32_t*>(&h);
}
__device__ __forceinline__ float ex2f(float x) {
    float r; asm("ex2.approx.f32 %0, %1;" : "=f"(r) : "f"(x)); return r;
}
__device__ __forceinline__ void stcs2(float* p, float a, float b) {
    asm volatile("st.global.cs.v2.f32 [%0], {%1, %2};" :: "l"(p), "f"(a), "f"(b) : "memory");
}
__device__ __forceinline__ void ldsm4(uint32_t* r, uint32_t a) {
    asm volatile("ldmatrix.sync.aligned.m8n8.x4.shared.b16 {%0,%1,%2,%3}, [%4];"
        : "=r"(r[0]), "=r"(r[1]), "=r"(r[2]), "=r"(r[3]) : "r"(a));
}
__device__ __forceinline__ void ldsm4t(uint32_t* r, uint32_t a) {
    asm volatile("ldmatrix.sync.aligned.m8n8.x4.trans.shared.b16 {%0,%1,%2,%3}, [%4];"
        : "=r"(r[0]), "=r"(r[1]), "=r"(r[2]), "=r"(r[3]) : "r"(a));
}
__device__ __forceinline__ void mma16816(float* d, const uint32_t* a, const uint32_t* b) {
    asm volatile("mma.sync.aligned.m16n8k16.row.col.f32.f16.f16.f32 "
        "{%0,%1,%2,%3},{%4,%5,%6,%7},{%8,%9},{%0,%1,%2,%3};"
        : "+f"(d[0]), "+f"(d[1]), "+f"(d[2]), "+f"(d[3])
        : "r"(a[0]), "r"(a[1]), "r"(a[2]), "r"(a[3]), "r"(b[0]), "r"(b[1]));
}
__device__ __forceinline__ void cpa16(uint32_t dst, const void* src) {   // L2-only fill
    asm volatile("cp.async.cg.shared.global [%0], [%1], 16;" :: "r"(dst), "l"(src));
}
#define CPA_COMMIT() asm volatile("cp.async.commit_group;" ::: "memory")
#define CPA_WAIT0()  asm volatile("cp.async.wait_group 0;" ::: "memory")

// ---------------- prep kernels ----------------
__global__ void prep_cvt(const float4* __restrict__ Qs, const float4* __restrict__ Ks,
                         const float4* __restrict__ Vs) {
    const size_t n1 = (size_t)BHn * Sn * Dn / 8;
    size_t i = (size_t)blockIdx.x * blockDim.x + threadIdx.x;
    size_t tsel = i / n1, off = i - tsel * n1;
    const float4* src = tsel == 0 ? Qs : (tsel == 1 ? Ks : Vs);
    __half* dst = tsel == 0 ? QH_g : (tsel == 1 ? KH_g : VH_g);
    float4 a = src[off * 2], b = src[off * 2 + 1];
    uint4 o;
    o.x = ph2(a.x, a.y); o.y = ph2(a.z, a.w);
    o.z = ph2(b.x, b.y); o.w = ph2(b.z, b.w);
    reinterpret_cast<uint4*>(dst)[off] = o;
}
__global__ void prep_bias(const int* __restrict__ Mk) {
    int i = blockIdx.x * blockDim.x + threadIdx.x;
    if (i < Bn * Sn) BIAS_g[i] = Mk[i] ? 0.f : -1e30f;
}

// ================= Kernel A: rowsums at high occupancy =================
#define A_QH   0
#define A_KH   16384
#define A_BIAS 32768
#define A_RS   40960
#define A_SMEM 41472

__global__ __launch_bounds__(256, 3)
void rowsum_k(void)
{
    extern __shared__ char smem[];
    const uint32_t su = s2u(smem);
    const int tid = threadIdx.x, w = tid >> 5, lane = tid & 31;
    const int bh = blockIdx.y, b = bh >> 4;
    const int q0 = blockIdx.x * MQ;
    const __half* Kg = KH_g + (size_t)bh * Sn * Dn;

    {
        const __half* qg = QH_g + ((size_t)bh * Sn + q0) * Dn;
        #pragma unroll
        for (int it = 0; it < 4; ++it) {
            int ch = tid + it * 256;
            int r = ch >> 3, c8 = ch & 7;
            cpa16(su + A_QH + swz((uint32_t)(r * 128 + c8 * 16)), qg + r * Dn + c8 * 8);
        }
        const float* bg = BIAS_g + b * Sn;
        #pragma unroll
        for (int it = 0; it < 2; ++it) {
            int ch = tid + it * 256;
            cpa16(su + A_BIAS + (uint32_t)ch * 16, bg + ch * 4);
        }
        CPA_COMMIT();
    }
    #pragma unroll
    for (int it = 0; it < 2; ++it) {
        int ch = tid + it * 256;
        int r = ch >> 3, c8 = ch & 7;
        cpa16(su + A_KH + swz((uint32_t)(r * 128 + c8 * 16)), Kg + r * Dn + c8 * 8);
    }
    CPA_COMMIT();
    CPA_WAIT0();
    __syncthreads();

    const float* bias = (const float*)(smem + A_BIAS);
    const int qr = w * 16 + (lane & 7) + ((lane >> 3) & 1) * 8;
    const uint32_t qcs = ((lane >> 4) & 1) * 16;
    const int krb = (lane & 7) + ((lane >> 4) & 1) * 8;
    const uint32_t kcs = ((lane >> 3) & 1) * 16;
    const int cb0 = (lane & 3) * 2;

    uint32_t qf[4][4];
    #pragma unroll
    for (int ks = 0; ks < 4; ++ks)
        ldsm4(qf[ks], su + A_QH + swz((uint32_t)(qr * 128 + ks * 32) + qcs));

    float rs0 = 0.f, rs1 = 0.f;
    for (int t = 0; t < NTILES; ++t) {
        if (t + 1 < NTILES) {
            const __half* kg = Kg + (size_t)(t + 1) * TN * Dn;
            uint32_t buf = su + A_KH + ((t + 1) & 1) * 8192;
            #pragma unroll
            for (int it = 0; it < 2; ++it) {
                int ch = tid + it * 256;
                int r = ch >> 3, c8 = ch & 7;
                cpa16(buf + swz((uint32_t)(r * 128 + c8 * 16)), kg + r * Dn + c8 * 8);
            }
            CPA_COMMIT();
        }
        const uint32_t kbuf = su + A_KH + (t & 1) * 8192;
        float c_[8][4];
        #pragma unroll
        for (int nt = 0; nt < 8; ++nt)
            #pragma unroll
            for (int i = 0; i < 4; ++i) c_[nt][i] = 0.f;
        #pragma unroll
        for (int ks = 0; ks < 4; ++ks) {
            #pragma unroll
            for (int pr = 0; pr < 4; ++pr) {
                uint32_t bh_[4];
                ldsm4(bh_, kbuf + swz((uint32_t)((pr * 16 + krb) * 128 + ks * 32) + kcs));
                mma16816(c_[2 * pr],     qf[ks], bh_);
                mma16816(c_[2 * pr + 1], qf[ks], bh_ + 2);
            }
        }
        const float* bp = bias + t * TN + cb0;
        #pragma unroll
        for (int nt = 0; nt < 8; ++nt) {
            float2 bb = *(const float2*)(bp + nt * 8);
            rs0 += ex2f(fmaf(c_[nt][0], C2, bb.x)) + ex2f(fmaf(c_[nt][1], C2, bb.y));
            rs1 += ex2f(fmaf(c_[nt][2], C2, bb.x)) + ex2f(fmaf(c_[nt][3], C2, bb.y));
        }
        if (t + 1 < NTILES) { CPA_WAIT0(); __syncthreads(); }
    }
    rs0 += __shfl_xor_sync(~0u, rs0, 1); rs0 += __shfl_xor_sync(~0u, rs0, 2);
    rs1 += __shfl_xor_sync(~0u, rs1, 1); rs1 += __shfl_xor_sync(~0u, rs1, 2);
    float* rsm = (float*)(smem + A_RS);
    if ((lane & 3) == 0) {
        rsm[w * 16 + (lane >> 2)] = rs0;
        rsm[w * 16 + 8 + (lane >> 2)] = rs1;
    }
    __syncthreads();
    if (tid < MQ)
        INV_g[(size_t)bh * Sn + q0 + tid] = 1.0f / rsm[tid];
}

// ================= Kernel B: attn + O =================
#define NT 128
#define SM_QH   0
#define SM_KH   16384
#define SM_VH   32768
#define SM_BIAS 49152
#define SMEM_B  57344      // x3 CTAs = 172032

__device__ __forceinline__ void issue_tile(uint32_t bufbase, const __half* __restrict__ g, int tid) {
    #pragma unroll
    for (int it = 0; it < 4; ++it) {
        int ch = tid + it * NT;
        int r = ch >> 3, c8 = ch & 7;
        cpa16(bufbase + swz((uint32_t)(r * 128 + c8 * 16)), g + r * Dn + c8 * 8);
    }
}

__global__ __launch_bounds__(NT, 3)
void attn_hmma(float* __restrict__ Out, float* __restrict__ Attn)
{
    extern __shared__ char smem[];
    const uint32_t su = s2u(smem);
    const int tid = threadIdx.x, w = tid >> 5, lane = tid & 31;
    const int bh = blockIdx.y, b = bh >> 4;
    const int q0 = blockIdx.x * MQ;

    const __half* Kg = KH_g + (size_t)bh * Sn * Dn;
    const __half* Vg = VH_g + (size_t)bh * Sn * Dn;

    {
        const __half* qg = QH_g + ((size_t)bh * Sn + q0) * Dn;
        #pragma unroll
        for (int it = 0; it < 8; ++it) {
            int ch = tid + it * NT;
            int r = ch >> 3, c8 = ch & 7;
            cpa16(su + SM_QH + swz((uint32_t)(r * 128 + c8 * 16)), qg + r * Dn + c8 * 8);
        }
        const float* bg = BIAS_g + b * Sn;
        #pragma unroll
        for (int it = 0; it < 4; ++it) {
            int ch = tid + it * NT;
            cpa16(su + SM_BIAS + (uint32_t)ch * 16, bg + ch * 4);
        }
        CPA_COMMIT();
    }
    issue_tile(su + SM_KH, Kg, tid);
    issue_tile(su + SM_VH, Vg, tid);
    CPA_COMMIT();

    const uint32_t qcs = ((lane >> 4) & 1) * 16;
    const int krb = (lane & 7) + ((lane >> 4) & 1) * 8;
    const uint32_t kcs = ((lane >> 3) & 1) * 16;
    const int cb0 = (lane & 3) * 2;
    int qr[2];
    qr[0] = w * 16 + (lane & 7) + ((lane >> 3) & 1) * 8;
    qr[1] = qr[0] + 64;

    float inv_[2][2];
    {
        const float* ig = INV_g + (size_t)bh * Sn + q0;
        #pragma unroll
        for (int mb = 0; mb < 2; ++mb) {
            inv_[mb][0] = __ldg(ig + (w + 4 * mb) * 16 + (lane >> 2));
            inv_[mb][1] = __ldg(ig + (w + 4 * mb) * 16 + 8 + (lane >> 2));
        }
    }
    CPA_WAIT0();
    __syncthreads();
    const float* bias = (const float*)(smem + SM_BIAS);

    float O[2][8][4];
    #pragma unroll
    for (int mb = 0; mb < 2; ++mb)
        #pragma unroll
        for (int j = 0; j < 8; ++j)
            #pragma unroll
            for (int i = 0; i < 4; ++i) O[mb][j][i] = 0.f;

    const int vrb = (lane & 7) + ((lane >> 3) & 1) * 8;
    const uint32_t vcs = ((lane >> 4) & 1) * 16;
    float* ar[2][2];
    #pragma unroll
    for (int mb = 0; mb < 2; ++mb) {
        ar[mb][0] = Attn + ((size_t)bh * Sn + q0 + (w + 4 * mb) * 16 + (lane >> 2)) * Sn;
        ar[mb][1] = ar[mb][0] + (size_t)8 * Sn;
    }

    for (int t = 0; t < NTILES; ++t) {
        if (t + 1 < NTILES) {
            issue_tile(su + SM_KH + ((t + 1) & 1) * 8192, Kg + (size_t)(t + 1) * TN * Dn, tid);
            issue_tile(su + SM_VH + ((t + 1) & 1) * 8192, Vg + (size_t)(t + 1) * TN * Dn, tid);
            CPA_COMMIT();
        }
        const uint32_t kbuf = su + SM_KH + (t & 1) * 8192;
        const uint32_t vbuf = su + SM_VH + (t & 1) * 8192;

        float c_[2][8][4];
        #pragma unroll
        for (int mb = 0; mb < 2; ++mb)
            #pragma unroll
            for (int nt = 0; nt < 8; ++nt)
                #pragma unroll
                for (int i = 0; i < 4; ++i) c_[mb][nt][i] = 0.f;
        #pragma unroll
        for (int ks = 0; ks < 4; ++ks) {
            uint32_t ah[2][4];
            #pragma unroll
            for (int mb = 0; mb < 2; ++mb)
                ldsm4(ah[mb], su + SM_QH + swz((uint32_t)(qr[mb] * 128 + ks * 32) + qcs));
            #pragma unroll
            for (int pr = 0; pr < 4; ++pr) {
                uint32_t bh_[4];
                ldsm4(bh_, kbuf + swz((uint32_t)((pr * 16 + krb) * 128 + ks * 32) + kcs));
                #pragma unroll
                for (int mb = 0; mb < 2; ++mb) {
                    mma16816(c_[mb][2 * pr],     ah[mb], bh_);
                    mma16816(c_[mb][2 * pr + 1], ah[mb], bh_ + 2);
                }
            }
        }
        uint32_t PH[2][8][2];
        const float* bp = bias + t * TN + cb0;
        #pragma unroll
        for (int mb = 0; mb < 2; ++mb) {
            #pragma unroll
            for (int nt = 0; nt < 8; ++nt) {
                int col = t * TN + nt * 8 + cb0;
                float2 bb = *(const float2*)(bp + nt * 8);
                float p0 = ex2f(fmaf(c_[mb][nt][0], C2, bb.x)) * inv_[mb][0];
                float p1 = ex2f(fmaf(c_[mb][nt][1], C2, bb.y)) * inv_[mb][0];
                float p2 = ex2f(fmaf(c_[mb][nt][2], C2, bb.x)) * inv_[mb][1];
                float p3 = ex2f(fmaf(c_[mb][nt][3], C2, bb.y)) * inv_[mb][1];
                stcs2(ar[mb][0] + col, p0, p1);    // streaming store: don't pollute L2
                stcs2(ar[mb][1] + col, p2, p3);
                PH[mb][nt][0] = ph2(p0, p1);
                PH[mb][nt][1] = ph2(p2, p3);
            }
        }
        #pragma unroll
        for (int kp = 0; kp < 4; ++kp) {
            uint32_t pah[2][4];
            #pragma unroll
            for (int mb = 0; mb < 2; ++mb) {
                pah[mb][0] = PH[mb][2*kp][0];   pah[mb][1] = PH[mb][2*kp][1];
                pah[mb][2] = PH[mb][2*kp+1][0]; pah[mb][3] = PH[mb][2*kp+1][1];
            }
            int vrow = kp * 16 + vrb;
            #pragma unroll
            for (int dp = 0; dp < 4; ++dp) {
                uint32_t vb[4];
                ldsm4t(vb, vbuf + swz((uint32_t)(vrow * 128 + dp * 32) + vcs));
                #pragma unroll
                for (int mb = 0; mb < 2; ++mb) {
                    mma16816(O[mb][2 * dp],     pah[mb], vb);
                    mma16816(O[mb][2 * dp + 1], pah[mb], vb + 2);
                }
            }
        }
        if (t + 1 < NTILES) { CPA_WAIT0(); __syncthreads(); }
    }

    #pragma unroll
    for (int mb = 0; mb < 2; ++mb) {
        float* orow0 = Out + ((size_t)bh * Sn + q0 + (w + 4 * mb) * 16 + (lane >> 2)) * Dn;
        float* orow1 = orow0 + 8 * Dn;
        #pragma unroll
        for (int dt = 0; dt < 8; ++dt) {
            int col = dt * 8 + cb0;
            stcs2(orow0 + col, O[mb][dt][0], O[mb][dt][1]);
            stcs2(orow1 + col, O[mb][dt][2], O[mb][dt][3]);
        }
    }
}

extern "C" void kernel_launch(void* const* d_in, const int* in_sizes, int n_in,
                              void* d_out, int out_size)
{
    const float* Q    = (const float*)d_in[0];
    const float* K    = (const float*)d_in[1];
    const float* V    = (const float*)d_in[2];
    const int*   mask = (const int*)d_in[3];

    float* Out  = (float*)d_out;
    float* Attn = Out + (size_t)BHn * Sn * Dn;

    const size_t nchunks = (size_t)3 * BHn * Sn * Dn / 8;
    prep_cvt<<<(int)(nchunks / 256), 256>>>((const float4*)Q, (const float4*)K, (const float4*)V);
    prep_bias<<<(Bn * Sn + 255) / 256, 256>>>(mask);

    cudaFuncSetAttribute(rowsum_k, cudaFuncAttributeMaxDynamicSharedMemorySize, A_SMEM);
    cudaFuncSetAttribute(attn_hmma, cudaFuncAttributeMaxDynamicSharedMemorySize, SMEM_B);

    dim3 grid(Sn / MQ, BHn);
    rowsum_k<<<grid, 256, A_SMEM>>>();
    attn_hmma<<<grid, NT, SMEM_B>>>(Out, Attn);
}